// round 14
// baseline (speedup 1.0000x reference)
#include <cuda_runtime.h>
#include <cuda_fp16.h>
#include <cstdint>

#define DINLINE __device__ __forceinline__

// Fixed problem shapes (Int8DynActInt4WeightLinear: B=4,S=2048,IN=OUT=4096,G=256)
constexpr int K_DIM  = 4096;
constexpr int N_DIM  = 4096;
constexpr int M_MAX  = 8192;
constexpr int NGROUP = 16;   // K_DIM / 256

// Scratch (device globals — no allocation allowed)
__device__ __align__(16) int8_t g_wq8[(size_t)N_DIM * K_DIM]; // (w - z) int8, exact, [N,K]
__device__ __align__(16) int8_t g_aq8[(size_t)M_MAX * K_DIM]; // q int8, exact, [M,K]
__device__ float g_xscale[M_MAX];  // per-token activation scale
__device__ float g_xzp  [M_MAX];   // per-token zero point (integral float)
__device__ float g_crow [N_DIM];   // C[n] = sum_k (w-z)[n,k]*s_w[n,g(k)]
__device__ int   g_wfmt;           // 0=int8, 1=int32, 2=float32

// ---------------------------------------------------------------------------
// helpers
// ---------------------------------------------------------------------------
DINLINE uint32_t smem_u32(const void* p) { return (uint32_t)__cvta_generic_to_shared(p); }

DINLINE void cp16(uint32_t dst_smem, const void* src) {
    asm volatile("cp.async.cg.shared.global [%0], [%1], 16;"
                 :: "r"(dst_smem), "l"(__cvta_generic_to_global(src)) : "memory");
}

DINLINE void ldm4(uint32_t* r, uint32_t addr) {
    asm volatile("ldmatrix.sync.aligned.m8n8.x4.shared.b16 {%0,%1,%2,%3}, [%4];"
                 : "=r"(r[0]), "=r"(r[1]), "=r"(r[2]), "=r"(r[3]) : "r"(addr));
}

// int8 MMA: D(s32) += A(s8,16x32) * B(s8,32x8)
DINLINE void mmas8(int* d, const uint32_t* a, uint32_t b0, uint32_t b1) {
    asm volatile(
        "mma.sync.aligned.m16n8k32.row.col.s32.s8.s8.s32 "
        "{%0,%1,%2,%3}, {%4,%5,%6,%7}, {%8,%9}, {%0,%1,%2,%3};"
        : "+r"(d[0]), "+r"(d[1]), "+r"(d[2]), "+r"(d[3])
        : "r"(a[0]), "r"(a[1]), "r"(a[2]), "r"(a[3]), "r"(b0), "r"(b1));
}

// ---------------------------------------------------------------------------
// Kernel 0: detect the on-device dtype of the weight buffer.
// ---------------------------------------------------------------------------
__global__ void detect_wfmt_kernel(const int* __restrict__ w)
{
    int alli32 = 1, allf32 = 1;
    for (int i = threadIdx.x; i < 4096; i += 256) {
        int u = w[i];
        alli32 &= (u >= -8 && u <= 7);
        float f = __int_as_float(u);
        allf32 &= (isfinite(f) && fabsf(f) <= 8.0f && f == rintf(f));
    }
    alli32 = __syncthreads_and(alli32);
    allf32 = __syncthreads_and(allf32);
    if (threadIdx.x == 0)
        g_wfmt = alli32 ? 1 : (allf32 ? 2 : 0);
}

// ---------------------------------------------------------------------------
// Kernel 1: weight prep  wq8[o,k] = w - z[o,g]   (int8, exact; z is integral)
// ---------------------------------------------------------------------------
__global__ void __launch_bounds__(256) prep_w_kernel(
    const void* __restrict__ wraw, const float* __restrict__ zeros)
{
    size_t t = (size_t)blockIdx.x * 256 + threadIdx.x;
    size_t base = t * 8;
    if (base >= (size_t)N_DIM * K_DIM) return;
    int o = (int)(base >> 12);
    int g = (int)((base >> 8) & 15);
    const int zi = (int)zeros[o * NGROUP + g];   // integral by construction

    int wv[8];
    const int fmt = g_wfmt;
    if (fmt == 1) {
        const int4* p = reinterpret_cast<const int4*>((const int*)wraw + base);
        int4 a = p[0], b = p[1];
        wv[0] = a.x; wv[1] = a.y; wv[2] = a.z; wv[3] = a.w;
        wv[4] = b.x; wv[5] = b.y; wv[6] = b.z; wv[7] = b.w;
    } else if (fmt == 2) {
        const float4* p = reinterpret_cast<const float4*>((const float*)wraw + base);
        float4 a = p[0], b = p[1];
        wv[0] = (int)a.x; wv[1] = (int)a.y; wv[2] = (int)a.z; wv[3] = (int)a.w;
        wv[4] = (int)b.x; wv[5] = (int)b.y; wv[6] = (int)b.z; wv[7] = (int)b.w;
    } else {
        int2 r = *reinterpret_cast<const int2*>((const int8_t*)wraw + base);
#pragma unroll
        for (int i = 0; i < 4; i++) wv[i]     = (r.x << ((3 - i) * 8)) >> 24;
#pragma unroll
        for (int i = 0; i < 4; i++) wv[4 + i] = (r.y << ((3 - i) * 8)) >> 24;
    }

#pragma unroll
    for (int i = 0; i < 8; i++) wv[i] -= zi;     // [-10, 9]
    uint32_t lo = (wv[0] & 0xff) | ((wv[1] & 0xff) << 8) |
                  ((wv[2] & 0xff) << 16) | ((uint32_t)wv[3] << 24);
    uint32_t hi = (wv[4] & 0xff) | ((wv[5] & 0xff) << 8) |
                  ((wv[6] & 0xff) << 16) | ((uint32_t)wv[7] << 24);
    uint2 u; u.x = lo; u.y = hi;
    *reinterpret_cast<uint2*>(g_wq8 + base) = u;
}

// ---------------------------------------------------------------------------
// Kernel 1b: C[n] = sum_g s_w[n,g] * sum_{k in g} (w-z)[n,k]    (one block/row)
// ---------------------------------------------------------------------------
__global__ void __launch_bounds__(256) wrowsum_kernel(const float* __restrict__ scales)
{
    const int n = blockIdx.x, t = threadIdx.x;
    const int4 v = reinterpret_cast<const int4*>(g_wq8 + (size_t)n * K_DIM)[t];
    int s = __dp4a(v.x, 0x01010101, 0);
    s = __dp4a(v.y, 0x01010101, s);
    s = __dp4a(v.z, 0x01010101, s);
    s = __dp4a(v.w, 0x01010101, s);                 // 16 int8 of one group
    float partial = (float)s * scales[n * NGROUP + (t >> 4)];
#pragma unroll
    for (int off = 16; off > 0; off >>= 1)
        partial += __shfl_xor_sync(0xffffffffu, partial, off);
    __shared__ float sw[8];
    if ((t & 31) == 0) sw[t >> 5] = partial;
    __syncthreads();
    if (t == 0) {
        float c = 0.0f;
#pragma unroll
        for (int i = 0; i < 8; i++) c += sw[i];
        g_crow[n] = c;
    }
}

// ---------------------------------------------------------------------------
// Kernel 2: per-token asymmetric int8 fake-quant -> q int8 (exact), scale, zp
// ---------------------------------------------------------------------------
__global__ void __launch_bounds__(128) quant_x_kernel(const float* __restrict__ x)
{
    const int row = blockIdx.x;
    const int tid = threadIdx.x;
    const float4* xv = reinterpret_cast<const float4*>(x + (size_t)row * K_DIM);

    float4 v[8];
    float mn = 0.0f, mx = 0.0f;
#pragma unroll
    for (int j = 0; j < 8; j++) {
        v[j] = xv[tid + 128 * j];
        mn = fminf(mn, fminf(fminf(v[j].x, v[j].y), fminf(v[j].z, v[j].w)));
        mx = fmaxf(mx, fmaxf(fmaxf(v[j].x, v[j].y), fmaxf(v[j].z, v[j].w)));
    }
#pragma unroll
    for (int off = 16; off > 0; off >>= 1) {
        mn = fminf(mn, __shfl_xor_sync(0xffffffffu, mn, off));
        mx = fmaxf(mx, __shfl_xor_sync(0xffffffffu, mx, off));
    }
    __shared__ float smn[4], smx[4], sparam[2];
    int wid = tid >> 5, lid = tid & 31;
    if (lid == 0) { smn[wid] = mn; smx[wid] = mx; }
    __syncthreads();
    if (tid == 0) {
        float a = fminf(fminf(smn[0], smn[1]), fminf(smn[2], smn[3]));
        float b = fmaxf(fmaxf(smx[0], smx[1]), fmaxf(smx[2], smx[3]));
        float scale = fmaxf(__fdiv_rn(b - a, 255.0f), 1.1920928955078125e-07f);
        float zp = -128.0f - rintf(__fdiv_rn(a, scale));
        zp = fminf(fmaxf(zp, -128.0f), 127.0f);
        sparam[0] = scale; sparam[1] = zp;
        g_xscale[row] = scale;
        g_xzp[row]    = zp;
    }
    __syncthreads();
    const float scale = sparam[0], zp = sparam[1];

    uint32_t* dst = reinterpret_cast<uint32_t*>(g_aq8 + (size_t)row * K_DIM);
#pragma unroll
    for (int j = 0; j < 8; j++) {
        int q0 = (int)fminf(fmaxf(rintf(__fdiv_rn(v[j].x, scale)) + zp, -128.0f), 127.0f);
        int q1 = (int)fminf(fmaxf(rintf(__fdiv_rn(v[j].y, scale)) + zp, -128.0f), 127.0f);
        int q2 = (int)fminf(fmaxf(rintf(__fdiv_rn(v[j].z, scale)) + zp, -128.0f), 127.0f);
        int q3 = (int)fminf(fmaxf(rintf(__fdiv_rn(v[j].w, scale)) + zp, -128.0f), 127.0f);
        dst[tid + 128 * j] = (q0 & 0xff) | ((q1 & 0xff) << 8) |
                             ((q2 & 0xff) << 16) | ((uint32_t)q3 << 24);
    }
}

// ---------------------------------------------------------------------------
// Kernel 3: int8 IMMA GEMM (mma.m16n8k32.s8), CTA 128x128, BK=128 (bytes),
// 4-stage cp.async, Swizzle<3,4,3>, 8 warps (2M x 4N), warp 64x32.
// Groupwise fp32 rescale every 2 chunks (256 k). Epilogue applies zp/C/bias.
// ---------------------------------------------------------------------------
constexpr int BM = 128, BN = 128, STAGES = 4;
constexpr int STAGE_B   = (BM + BN) * 128;          // 32 KB (int8 rows of 128B)
constexpr int SW_BYTES  = NGROUP * BN * 4;          // 8 KB group scales
constexpr int GEMM_SMEM = STAGES * STAGE_B + SW_BYTES;
constexpr int NCH       = K_DIM / 128;              // 32 chunks of 128 k

__global__ void __launch_bounds__(256, 1) gemm_kernel(
    const float* __restrict__ scales, const float* __restrict__ bias,
    float* __restrict__ out)
{
    extern __shared__ char smem[];
    const uint32_t sb = smem_u32(smem);
    float* swsm = reinterpret_cast<float*>(smem + STAGES * STAGE_B);
    const int tid  = threadIdx.x;
    const int lane = tid & 31, wid = tid >> 5;
    const int wm = wid & 1;         // 0..1 -> 64-row slab
    const int wn = wid >> 1;        // 0..3 -> 32-col slab

    const int m0 = blockIdx.y * BM;
    const int n0 = blockIdx.x * BN;
    const char* Ab = reinterpret_cast<const char*>(g_aq8) + (size_t)m0 * K_DIM;
    const char* Bb = reinterpret_cast<const char*>(g_wq8) + (size_t)n0 * K_DIM;

    // preload group scales for this CTA's 128 columns: swsm[g*128 + col]
    for (int i = tid; i < NGROUP * BN; i += 256) {
        int col = i & 127, g = i >> 7;
        swsm[i] = scales[(size_t)(n0 + col) * NGROUP + g];
    }

    const int      lrow = tid >> 3;              // 0..31
    const uint32_t lcol = (uint32_t)(tid & 7) * 16;

    float facc[4][4][4];
    int   iacc[4][4][4];
#pragma unroll
    for (int a = 0; a < 4; a++)
#pragma unroll
        for (int b = 0; b < 4; b++)
#pragma unroll
            for (int c = 0; c < 4; c++) { facc[a][b][c] = 0.0f; iacc[a][b][c] = 0; }

    const int arow = wm * 64 + (lane & 15);
    const int brow = wn * 32 + (lane & 15);
    const uint32_t fcol = 16u * (uint32_t)(lane >> 4);

#define LOAD_STAGE(stage, chunk)                                               \
    do {                                                                       \
        uint32_t as_ = sb + (stage) * STAGE_B;                                 \
        uint32_t bs_ = as_ + BM * 128;                                         \
        const char* asrc = Ab + (chunk) * 128 + lcol;                          \
        const char* bsrc = Bb + (chunk) * 128 + lcol;                          \
        _Pragma("unroll")                                                      \
        for (int p = 0; p < 4; p++) {                                          \
            int r = lrow + 32 * p;                                             \
            uint32_t sc = lcol ^ (uint32_t)((r & 7) << 4);                     \
            cp16(as_ + (uint32_t)r * 128 + sc, asrc + (size_t)r * K_DIM);      \
            cp16(bs_ + (uint32_t)r * 128 + sc, bsrc + (size_t)r * K_DIM);      \
        }                                                                      \
    } while (0)

#pragma unroll
    for (int s = 0; s < STAGES - 1; s++) {
        LOAD_STAGE(s, s);
        asm volatile("cp.async.commit_group;" ::: "memory");
    }

    for (int i = 0; i < NCH; i++) {
        asm volatile("cp.async.wait_group %0;" :: "n"(STAGES - 2) : "memory");
        __syncthreads();

        const int nx = i + STAGES - 1;
        if (nx < NCH) LOAD_STAGE(nx & (STAGES - 1), nx);
        asm volatile("cp.async.commit_group;" ::: "memory");

        const uint32_t as_ = sb + (i & (STAGES - 1)) * STAGE_B;
        const uint32_t bs_ = as_ + BM * 128;
#pragma unroll
        for (int ks = 0; ks < 4; ks++) {          // 4 x k32 per 128-k chunk
            uint32_t af[4][4], bf[2][4];
            const uint32_t cb = fcol + (uint32_t)(ks * 32);
#pragma unroll
            for (int mi = 0; mi < 4; mi++) {
                int r = arow + mi * 16;
                ldm4(af[mi], as_ + (uint32_t)r * 128 + (cb ^ (uint32_t)((r & 7) << 4)));
            }
#pragma unroll
            for (int njp = 0; njp < 2; njp++) {
                int r = brow + njp * 16;
                ldm4(bf[njp], bs_ + (uint32_t)r * 128 + (cb ^ (uint32_t)((r & 7) << 4)));
            }
#pragma unroll
            for (int mi = 0; mi < 4; mi++)
#pragma unroll
                for (int nj = 0; nj < 4; nj++)
                    mmas8(iacc[mi][nj], af[mi], bf[nj >> 1][nj & 1], bf[nj >> 1][2 + (nj & 1)]);
        }

        if (i & 1) {                               // end of group g = i>>1 (256 k)
            const int g = i >> 1;
#pragma unroll
            for (int nj = 0; nj < 4; nj++) {
                const float2 sw2 = *reinterpret_cast<const float2*>(
                    swsm + g * 128 + wn * 32 + nj * 8 + 2 * (lane & 3));
#pragma unroll
                for (int mi = 0; mi < 4; mi++) {
                    facc[mi][nj][0] += sw2.x * (float)iacc[mi][nj][0];
                    facc[mi][nj][1] += sw2.y * (float)iacc[mi][nj][1];
                    facc[mi][nj][2] += sw2.x * (float)iacc[mi][nj][2];
                    facc[mi][nj][3] += sw2.y * (float)iacc[mi][nj][3];
                    iacc[mi][nj][0] = 0; iacc[mi][nj][1] = 0;
                    iacc[mi][nj][2] = 0; iacc[mi][nj][3] = 0;
                }
            }
        }
    }
#undef LOAD_STAGE

    // Epilogue: out = s_x[m] * (facc - zp[m]*C[n]) + bias[n]
#pragma unroll
    for (int mi = 0; mi < 4; mi++) {
        const int grow_lo = m0 + wm * 64 + mi * 16 + (lane >> 2);
        const int grow_hi = grow_lo + 8;
        const float sl = g_xscale[grow_lo], zl = g_xzp[grow_lo];
        const float sh = g_xscale[grow_hi], zh = g_xzp[grow_hi];
        float* orow_lo = out + (size_t)grow_lo * N_DIM;
        float* orow_hi = out + (size_t)grow_hi * N_DIM;
#pragma unroll
        for (int nj = 0; nj < 4; nj++) {
            const int gcol = n0 + wn * 32 + nj * 8 + 2 * (lane & 3);
            float2 bv = *reinterpret_cast<const float2*>(bias + gcol);
            float2 cv = *reinterpret_cast<const float2*>(g_crow + gcol);
            float2 o0, o1;
            o0.x = sl * (facc[mi][nj][0] - zl * cv.x) + bv.x;
            o0.y = sl * (facc[mi][nj][1] - zl * cv.y) + bv.y;
            o1.x = sh * (facc[mi][nj][2] - zh * cv.x) + bv.x;
            o1.y = sh * (facc[mi][nj][3] - zh * cv.y) + bv.y;
            *reinterpret_cast<float2*>(orow_lo + gcol) = o0;
            *reinterpret_cast<float2*>(orow_hi + gcol) = o1;
        }
    }
}

// ---------------------------------------------------------------------------
// launch
// ---------------------------------------------------------------------------
extern "C" void kernel_launch(void* const* d_in, const int* in_sizes, int n_in,
                              void* d_out, int out_size)
{
    const float* x      = (const float*)d_in[0];
    const void*  w      = d_in[1];                 // dtype detected on device
    const float* scales = (const float*)d_in[2];
    const float* zeros  = (const float*)d_in[3];
    const float* bias   = (const float*)d_in[4];
    float*       out    = (float*)d_out;

    const int rows = in_sizes[0] / K_DIM;   // 8192 tokens

    detect_wfmt_kernel<<<1, 256>>>((const int*)w);

    {
        int total = (N_DIM * K_DIM) / 8;
        prep_w_kernel<<<(total + 255) / 256, 256>>>(w, zeros);
    }
    wrowsum_kernel<<<N_DIM, 256>>>(scales);
    quant_x_kernel<<<rows, 128>>>(x);

    cudaFuncSetAttribute(gemm_kernel, cudaFuncAttributeMaxDynamicSharedMemorySize, GEMM_SMEM);
    dim3 grid(N_DIM / BN, rows / BM);
    gemm_kernel<<<grid, 256, GEMM_SMEM>>>(scales, bias, out);
}

// round 15
// speedup vs baseline: 2.9340x; 2.9340x over previous
#include <cuda_runtime.h>
#include <cuda_fp16.h>
#include <cstdint>

#define DINLINE __device__ __forceinline__

// Fixed problem shapes (Int8DynActInt4WeightLinear: B=4,S=2048,IN=OUT=4096,G=256)
constexpr int K_DIM  = 4096;
constexpr int N_DIM  = 4096;
constexpr int M_MAX  = 8192;
constexpr int NGROUP = 16;   // K_DIM / 256

// Scratch (device globals — no allocation allowed)
__device__ __align__(16) __half g_wdq[(size_t)N_DIM * K_DIM]; // (w-z)*s_w fp16, [N,K]
__device__ __align__(16) __half g_aq [(size_t)M_MAX * K_DIM]; // (q-zp) integer-valued fp16, [M,K]
__device__ float g_xscale[M_MAX];                             // per-token activation scale
__device__ int   g_wfmt;                                      // 0=int8, 1=int32, 2=float32

// ---------------------------------------------------------------------------
// helpers
// ---------------------------------------------------------------------------
DINLINE uint32_t smem_u32(const void* p) { return (uint32_t)__cvta_generic_to_shared(p); }

DINLINE void cp16(uint32_t dst_smem, const void* src) {
    asm volatile("cp.async.cg.shared.global [%0], [%1], 16;"
                 :: "r"(dst_smem), "l"(__cvta_generic_to_global(src)) : "memory");
}

DINLINE void ldm4(uint32_t* r, uint32_t addr) {
    asm volatile("ldmatrix.sync.aligned.m8n8.x4.shared.b16 {%0,%1,%2,%3}, [%4];"
                 : "=r"(r[0]), "=r"(r[1]), "=r"(r[2]), "=r"(r[3]) : "r"(addr));
}

DINLINE void mma16816(float* d, const uint32_t* a, uint32_t b0, uint32_t b1) {
    asm volatile(
        "mma.sync.aligned.m16n8k16.row.col.f32.f16.f16.f32 "
        "{%0,%1,%2,%3}, {%4,%5,%6,%7}, {%8,%9}, {%0,%1,%2,%3};"
        : "+f"(d[0]), "+f"(d[1]), "+f"(d[2]), "+f"(d[3])
        : "r"(a[0]), "r"(a[1]), "r"(a[2]), "r"(a[3]), "r"(b0), "r"(b1));
}

union H2U { __half2 h; uint32_t u; };

// ---------------------------------------------------------------------------
// Kernel 0: detect the on-device dtype of the weight buffer.
// ---------------------------------------------------------------------------
__global__ void detect_wfmt_kernel(const int* __restrict__ w)
{
    int alli32 = 1, allf32 = 1;
    for (int i = threadIdx.x; i < 4096; i += 256) {
        int u = w[i];
        alli32 &= (u >= -8 && u <= 7);
        float f = __int_as_float(u);
        allf32 &= (isfinite(f) && fabsf(f) <= 8.0f && f == rintf(f));
    }
    alli32 = __syncthreads_and(alli32);
    allf32 = __syncthreads_and(allf32);
    if (threadIdx.x == 0)
        g_wfmt = alli32 ? 1 : (allf32 ? 2 : 0);
}

// ---------------------------------------------------------------------------
// Kernel 1: weight dequant  w'[o,k] = (w - zero[o,g]) * scale[o,g]  (fp16)
// ---------------------------------------------------------------------------
__global__ void __launch_bounds__(256) dequant_w_kernel(
    const void* __restrict__ wraw, const float* __restrict__ scales,
    const float* __restrict__ zeros)
{
    size_t t = (size_t)blockIdx.x * 256 + threadIdx.x;
    size_t base = t * 8;                          // 8 weight elements per thread
    if (base >= (size_t)N_DIM * K_DIM) return;
    int o = (int)(base >> 12);
    int g = (int)((base >> 8) & 15);
    float s = scales[o * NGROUP + g];
    float z = zeros [o * NGROUP + g];

    float f[8];
    const int fmt = g_wfmt;
    if (fmt == 1) {                               // int32 container
        const int4* p = reinterpret_cast<const int4*>((const int*)wraw + base);
        int4 a = p[0], b = p[1];
        f[0] = (float)a.x; f[1] = (float)a.y; f[2] = (float)a.z; f[3] = (float)a.w;
        f[4] = (float)b.x; f[5] = (float)b.y; f[6] = (float)b.z; f[7] = (float)b.w;
    } else if (fmt == 2) {                        // float32 container
        const float4* p = reinterpret_cast<const float4*>((const float*)wraw + base);
        float4 a = p[0], b = p[1];
        f[0] = a.x; f[1] = a.y; f[2] = a.z; f[3] = a.w;
        f[4] = b.x; f[5] = b.y; f[6] = b.z; f[7] = b.w;
    } else {                                      // raw int8
        int2 wv = *reinterpret_cast<const int2*>((const int8_t*)wraw + base);
#pragma unroll
        for (int i = 0; i < 4; i++) f[i]     = (float)((wv.x << ((3 - i) * 8)) >> 24);
#pragma unroll
        for (int i = 0; i < 4; i++) f[4 + i] = (float)((wv.y << ((3 - i) * 8)) >> 24);
    }

    H2U p0, p1, p2, p3;
    p0.h = __floats2half2_rn((f[0] - z) * s, (f[1] - z) * s);
    p1.h = __floats2half2_rn((f[2] - z) * s, (f[3] - z) * s);
    p2.h = __floats2half2_rn((f[4] - z) * s, (f[5] - z) * s);
    p3.h = __floats2half2_rn((f[6] - z) * s, (f[7] - z) * s);
    uint4 u; u.x = p0.u; u.y = p1.u; u.z = p2.u; u.w = p3.u;
    *reinterpret_cast<uint4*>(g_wdq + base) = u;
}

// ---------------------------------------------------------------------------
// Kernel 2: per-token asymmetric int8 fake-quant.
// Stores (q - zp) EXACTLY (integer value in fp16); scale applied in GEMM epilogue.
// ---------------------------------------------------------------------------
__global__ void __launch_bounds__(128) quant_x_kernel(const float* __restrict__ x)
{
    const int row = blockIdx.x;
    const int tid = threadIdx.x;
    const float4* xv = reinterpret_cast<const float4*>(x + (size_t)row * K_DIM);

    float4 v[8];
    float mn = 0.0f, mx = 0.0f;   // ref clamps min with 0 / max with 0
#pragma unroll
    for (int j = 0; j < 8; j++) {
        v[j] = xv[tid + 128 * j];
        mn = fminf(mn, fminf(fminf(v[j].x, v[j].y), fminf(v[j].z, v[j].w)));
        mx = fmaxf(mx, fmaxf(fmaxf(v[j].x, v[j].y), fmaxf(v[j].z, v[j].w)));
    }
#pragma unroll
    for (int off = 16; off > 0; off >>= 1) {
        mn = fminf(mn, __shfl_xor_sync(0xffffffffu, mn, off));
        mx = fmaxf(mx, __shfl_xor_sync(0xffffffffu, mx, off));
    }
    __shared__ float smn[4], smx[4], sparam[2];
    int wid = tid >> 5, lid = tid & 31;
    if (lid == 0) { smn[wid] = mn; smx[wid] = mx; }
    __syncthreads();
    if (tid == 0) {
        float a = fminf(fminf(smn[0], smn[1]), fminf(smn[2], smn[3]));
        float b = fmaxf(fmaxf(smx[0], smx[1]), fmaxf(smx[2], smx[3]));
        float scale = fmaxf(__fdiv_rn(b - a, 255.0f), 1.1920928955078125e-07f);
        float zp = -128.0f - rintf(__fdiv_rn(a, scale));
        zp = fminf(fmaxf(zp, -128.0f), 127.0f);
        sparam[0] = scale; sparam[1] = zp;
        g_xscale[row] = scale;
    }
    __syncthreads();
    const float scale = sparam[0], zp = sparam[1];

    uint2* dst = reinterpret_cast<uint2*>(g_aq + (size_t)row * K_DIM);
#pragma unroll
    for (int j = 0; j < 8; j++) {
        float q0 = fminf(fmaxf(rintf(__fdiv_rn(v[j].x, scale)) + zp, -128.0f), 127.0f);
        float q1 = fminf(fmaxf(rintf(__fdiv_rn(v[j].y, scale)) + zp, -128.0f), 127.0f);
        float q2 = fminf(fmaxf(rintf(__fdiv_rn(v[j].z, scale)) + zp, -128.0f), 127.0f);
        float q3 = fminf(fmaxf(rintf(__fdiv_rn(v[j].w, scale)) + zp, -128.0f), 127.0f);
        H2U a0, a1;                               // (q - zp): integer in [-255,255], exact in fp16
        a0.h = __floats2half2_rn(q0 - zp, q1 - zp);
        a1.h = __floats2half2_rn(q2 - zp, q3 - zp);
        uint2 u; u.x = a0.u; u.y = a1.u;
        dst[tid + 128 * j] = u;
    }
}

// ---------------------------------------------------------------------------
// Kernel 3: fp16 HMMA GEMM (mma.sync.m16n8k16), CTA tile 128x128, BK=64,
// 3-stage cp.async pipeline (96 KB SMEM -> 2 CTAs/SM), Swizzle<3,4,3>,
// 8 warps (2M x 4N), warp 64x32.   out[m,n] = xscale[m] * acc + bias[n]
// ---------------------------------------------------------------------------
constexpr int BM = 128, BN = 128, STAGES = 3;
constexpr int STAGE_B   = (BM + BN) * 128;        // 32 KB per stage
constexpr int GEMM_SMEM = STAGES * STAGE_B;       // 96 KB -> 2 CTAs/SM
constexpr int NCH       = K_DIM / 64;             // 64 chunks of 64 k

__global__ void __launch_bounds__(256, 2) gemm_kernel(
    const float* __restrict__ bias, float* __restrict__ out)
{
    extern __shared__ char smem[];
    const uint32_t sb = smem_u32(smem);
    const int tid  = threadIdx.x;
    const int lane = tid & 31, wid = tid >> 5;
    const int wm = wid & 1;         // 0..1  -> 64-row slab
    const int wn = wid >> 1;        // 0..3  -> 32-col slab

    const int m0 = blockIdx.y * BM;
    const int n0 = blockIdx.x * BN;
    const char* Ab = reinterpret_cast<const char*>(g_aq)  + (size_t)m0 * (K_DIM * 2);
    const char* Bb = reinterpret_cast<const char*>(g_wdq) + (size_t)n0 * (K_DIM * 2);

    // global->smem mapping: thread covers 4 (rowA,rowB) pairs of 16B
    const int      lrow = tid >> 3;           // 0..31
    const uint32_t lcol = (uint32_t)(tid & 7) * 16;

    float acc[4][4][4];
#pragma unroll
    for (int a = 0; a < 4; a++)
#pragma unroll
        for (int b = 0; b < 4; b++)
#pragma unroll
            for (int c = 0; c < 4; c++) acc[a][b][c] = 0.0f;

    // ldmatrix per-thread bases
    const int arow = wm * 64 + (lane & 15);            // + mi*16
    const int brow = wn * 32 + (lane & 15);            // + njp*16
    const uint32_t fcol = 16u * (uint32_t)(lane >> 4); // + ks*32

#define LOAD_STAGE(stage, chunk)                                               \
    do {                                                                       \
        uint32_t as_ = sb + (stage) * STAGE_B;                                 \
        uint32_t bs_ = as_ + BM * 128;                                         \
        const char* asrc = Ab + (chunk) * 128 + lcol;                          \
        const char* bsrc = Bb + (chunk) * 128 + lcol;                          \
        _Pragma("unroll")                                                      \
        for (int p = 0; p < 4; p++) {                                          \
            int r = lrow + 32 * p;                                             \
            uint32_t sc = lcol ^ (uint32_t)((r & 7) << 4);                     \
            cp16(as_ + (uint32_t)r * 128 + sc, asrc + (size_t)r * 8192);       \
            cp16(bs_ + (uint32_t)r * 128 + sc, bsrc + (size_t)r * 8192);       \
        }                                                                      \
    } while (0)

    // prologue: fill STAGES-1 = 2 stages
#pragma unroll
    for (int s = 0; s < STAGES - 1; s++) {
        LOAD_STAGE(s, s);
        asm volatile("cp.async.commit_group;" ::: "memory");
    }

    int cs = 0;                    // compute stage for chunk i
    int ls = STAGES - 1;           // load stage for chunk i+STAGES-1
    for (int i = 0; i < NCH; i++) {
        asm volatile("cp.async.wait_group %0;" :: "n"(STAGES - 2) : "memory");
        __syncthreads();

        const int nx = i + STAGES - 1;
        if (nx < NCH) LOAD_STAGE(ls, nx);
        asm volatile("cp.async.commit_group;" ::: "memory");
        ls = (ls + 1 == STAGES) ? 0 : ls + 1;

        const uint32_t as_ = sb + cs * STAGE_B;
        const uint32_t bs_ = as_ + BM * 128;
        cs = (cs + 1 == STAGES) ? 0 : cs + 1;
#pragma unroll
        for (int ks = 0; ks < 4; ks++) {
            uint32_t af[4][4], bf[2][4];
            const uint32_t cb = fcol + (uint32_t)(ks * 32);
#pragma unroll
            for (int mi = 0; mi < 4; mi++) {
                int r = arow + mi * 16;
                ldm4(af[mi], as_ + (uint32_t)r * 128 + (cb ^ (uint32_t)((r & 7) << 4)));
            }
#pragma unroll
            for (int njp = 0; njp < 2; njp++) {
                int r = brow + njp * 16;
                ldm4(bf[njp], bs_ + (uint32_t)r * 128 + (cb ^ (uint32_t)((r & 7) << 4)));
            }
#pragma unroll
            for (int mi = 0; mi < 4; mi++)
#pragma unroll
                for (int nj = 0; nj < 4; nj++)
                    mma16816(acc[mi][nj], af[mi], bf[nj >> 1][nj & 1], bf[nj >> 1][2 + (nj & 1)]);
        }
    }
#undef LOAD_STAGE

    // Epilogue: out = xscale[row] * acc + bias[col]
#pragma unroll
    for (int mi = 0; mi < 4; mi++) {
        const int grow_lo = m0 + wm * 64 + mi * 16 + (lane >> 2);
        const int grow_hi = grow_lo + 8;
        const float sl = g_xscale[grow_lo];
        const float sh = g_xscale[grow_hi];
        float* orow_lo = out + (size_t)grow_lo * N_DIM;
        float* orow_hi = out + (size_t)grow_hi * N_DIM;
#pragma unroll
        for (int nj = 0; nj < 4; nj++) {
            const int gcol = n0 + wn * 32 + nj * 8 + 2 * (lane & 3);
            float2 bv = *reinterpret_cast<const float2*>(bias + gcol);
            float2 o0, o1;
            o0.x = acc[mi][nj][0] * sl + bv.x;
            o0.y = acc[mi][nj][1] * sl + bv.y;
            o1.x = acc[mi][nj][2] * sh + bv.x;
            o1.y = acc[mi][nj][3] * sh + bv.y;
            *reinterpret_cast<float2*>(orow_lo + gcol) = o0;
            *reinterpret_cast<float2*>(orow_hi + gcol) = o1;
        }
    }
}

// ---------------------------------------------------------------------------
// launch
// ---------------------------------------------------------------------------
extern "C" void kernel_launch(void* const* d_in, const int* in_sizes, int n_in,
                              void* d_out, int out_size)
{
    const float* x      = (const float*)d_in[0];
    const void*  w      = d_in[1];                 // dtype detected on device
    const float* scales = (const float*)d_in[2];
    const float* zeros  = (const float*)d_in[3];
    const float* bias   = (const float*)d_in[4];
    float*       out    = (float*)d_out;

    const int rows = in_sizes[0] / K_DIM;   // 8192 tokens

    // 0) detect weight container dtype (int8 vs int32 vs float32)
    detect_wfmt_kernel<<<1, 256>>>((const int*)w);

    // 1) weight dequant -> fp16
    {
        int total = (N_DIM * K_DIM) / 8;
        dequant_w_kernel<<<(total + 255) / 256, 256>>>(w, scales, zeros);
    }
    // 2) activation fake-quant -> exact (q - zp) fp16 + per-row scale
    quant_x_kernel<<<rows, 128>>>(x);

    // 3) GEMM + scale + bias
    cudaFuncSetAttribute(gemm_kernel, cudaFuncAttributeMaxDynamicSharedMemorySize, GEMM_SMEM);
    dim3 grid(N_DIM / BN, rows / BM);
    gemm_kernel<<<grid, 256, GEMM_SMEM>>>(bias, out);
}

// round 16
// speedup vs baseline: 4.2658x; 1.4539x over previous
#include <cuda_runtime.h>
#include <cuda_fp16.h>
#include <cstdint>

#define DINLINE __device__ __forceinline__

// Fixed problem shapes (Int8DynActInt4WeightLinear: B=4,S=2048,IN=OUT=4096,G=256)
constexpr int K_DIM  = 4096;
constexpr int N_DIM  = 4096;
constexpr int M_MAX  = 8192;
constexpr int NGROUP = 16;   // K_DIM / 256

// Scratch (device globals — no allocation allowed)
__device__ __align__(16) __half g_wdq[(size_t)N_DIM * K_DIM]; // (w-z)*s_w fp16, [N,K]
__device__ __align__(16) __half g_aq [(size_t)M_MAX * K_DIM]; // (q-zp) integer-valued fp16, [M,K]
__device__ float g_xscale[M_MAX];                             // per-token activation scale
__device__ int   g_wfmt;                                      // 0=int8, 1=int32, 2=float32

// ---------------------------------------------------------------------------
// helpers
// ---------------------------------------------------------------------------
DINLINE uint32_t smem_u32(const void* p) { return (uint32_t)__cvta_generic_to_shared(p); }

DINLINE void cp16(uint32_t dst_smem, const void* src) {
    asm volatile("cp.async.cg.shared.global [%0], [%1], 16;"
                 :: "r"(dst_smem), "l"(__cvta_generic_to_global(src)) : "memory");
}

DINLINE void ldm4(uint32_t* r, uint32_t addr) {
    asm volatile("ldmatrix.sync.aligned.m8n8.x4.shared.b16 {%0,%1,%2,%3}, [%4];"
                 : "=r"(r[0]), "=r"(r[1]), "=r"(r[2]), "=r"(r[3]) : "r"(addr));
}

DINLINE void mma16816(float* d, const uint32_t* a, uint32_t b0, uint32_t b1) {
    asm volatile(
        "mma.sync.aligned.m16n8k16.row.col.f32.f16.f16.f32 "
        "{%0,%1,%2,%3}, {%4,%5,%6,%7}, {%8,%9}, {%0,%1,%2,%3};"
        : "+f"(d[0]), "+f"(d[1]), "+f"(d[2]), "+f"(d[3])
        : "r"(a[0]), "r"(a[1]), "r"(a[2]), "r"(a[3]), "r"(b0), "r"(b1));
}

union H2U { __half2 h; uint32_t u; };

// ---------------------------------------------------------------------------
// Kernel 0: detect the on-device dtype of the weight buffer.
// ---------------------------------------------------------------------------
__global__ void detect_wfmt_kernel(const int* __restrict__ w)
{
    int alli32 = 1, allf32 = 1;
    for (int i = threadIdx.x; i < 4096; i += 256) {
        int u = w[i];
        alli32 &= (u >= -8 && u <= 7);
        float f = __int_as_float(u);
        allf32 &= (isfinite(f) && fabsf(f) <= 8.0f && f == rintf(f));
    }
    alli32 = __syncthreads_and(alli32);
    allf32 = __syncthreads_and(allf32);
    if (threadIdx.x == 0)
        g_wfmt = alli32 ? 1 : (allf32 ? 2 : 0);
}

// ---------------------------------------------------------------------------
// Kernel 1: weight dequant  w'[o,k] = (w - zero[o,g]) * scale[o,g]  (fp16)
// ---------------------------------------------------------------------------
__global__ void __launch_bounds__(256) dequant_w_kernel(
    const void* __restrict__ wraw, const float* __restrict__ scales,
    const float* __restrict__ zeros)
{
    size_t t = (size_t)blockIdx.x * 256 + threadIdx.x;
    size_t base = t * 8;                          // 8 weight elements per thread
    if (base >= (size_t)N_DIM * K_DIM) return;
    int o = (int)(base >> 12);
    int g = (int)((base >> 8) & 15);
    float s = scales[o * NGROUP + g];
    float z = zeros [o * NGROUP + g];

    float f[8];
    const int fmt = g_wfmt;
    if (fmt == 1) {                               // int32 container
        const int4* p = reinterpret_cast<const int4*>((const int*)wraw + base);
        int4 a = p[0], b = p[1];
        f[0] = (float)a.x; f[1] = (float)a.y; f[2] = (float)a.z; f[3] = (float)a.w;
        f[4] = (float)b.x; f[5] = (float)b.y; f[6] = (float)b.z; f[7] = (float)b.w;
    } else if (fmt == 2) {                        // float32 container
        const float4* p = reinterpret_cast<const float4*>((const float*)wraw + base);
        float4 a = p[0], b = p[1];
        f[0] = a.x; f[1] = a.y; f[2] = a.z; f[3] = a.w;
        f[4] = b.x; f[5] = b.y; f[6] = b.z; f[7] = b.w;
    } else {                                      // raw int8
        int2 wv = *reinterpret_cast<const int2*>((const int8_t*)wraw + base);
#pragma unroll
        for (int i = 0; i < 4; i++) f[i]     = (float)((wv.x << ((3 - i) * 8)) >> 24);
#pragma unroll
        for (int i = 0; i < 4; i++) f[4 + i] = (float)((wv.y << ((3 - i) * 8)) >> 24);
    }

    H2U p0, p1, p2, p3;
    p0.h = __floats2half2_rn((f[0] - z) * s, (f[1] - z) * s);
    p1.h = __floats2half2_rn((f[2] - z) * s, (f[3] - z) * s);
    p2.h = __floats2half2_rn((f[4] - z) * s, (f[5] - z) * s);
    p3.h = __floats2half2_rn((f[6] - z) * s, (f[7] - z) * s);
    uint4 u; u.x = p0.u; u.y = p1.u; u.z = p2.u; u.w = p3.u;
    *reinterpret_cast<uint4*>(g_wdq + base) = u;
}

// ---------------------------------------------------------------------------
// Kernel 2: per-token asymmetric int8 fake-quant.
// Stores (q - zp) EXACTLY (integer value in fp16); scale applied in GEMM epilogue.
// ---------------------------------------------------------------------------
__global__ void __launch_bounds__(128) quant_x_kernel(const float* __restrict__ x)
{
    const int row = blockIdx.x;
    const int tid = threadIdx.x;
    const float4* xv = reinterpret_cast<const float4*>(x + (size_t)row * K_DIM);

    float4 v[8];
    float mn = 0.0f, mx = 0.0f;   // ref clamps min with 0 / max with 0
#pragma unroll
    for (int j = 0; j < 8; j++) {
        v[j] = xv[tid + 128 * j];
        mn = fminf(mn, fminf(fminf(v[j].x, v[j].y), fminf(v[j].z, v[j].w)));
        mx = fmaxf(mx, fmaxf(fmaxf(v[j].x, v[j].y), fmaxf(v[j].z, v[j].w)));
    }
#pragma unroll
    for (int off = 16; off > 0; off >>= 1) {
        mn = fminf(mn, __shfl_xor_sync(0xffffffffu, mn, off));
        mx = fmaxf(mx, __shfl_xor_sync(0xffffffffu, mx, off));
    }
    __shared__ float smn[4], smx[4], sparam[2];
    int wid = tid >> 5, lid = tid & 31;
    if (lid == 0) { smn[wid] = mn; smx[wid] = mx; }
    __syncthreads();
    if (tid == 0) {
        float a = fminf(fminf(smn[0], smn[1]), fminf(smn[2], smn[3]));
        float b = fmaxf(fmaxf(smx[0], smx[1]), fmaxf(smx[2], smx[3]));
        float scale = fmaxf(__fdiv_rn(b - a, 255.0f), 1.1920928955078125e-07f);
        float zp = -128.0f - rintf(__fdiv_rn(a, scale));
        zp = fminf(fmaxf(zp, -128.0f), 127.0f);
        sparam[0] = scale; sparam[1] = zp;
        g_xscale[row] = scale;
    }
    __syncthreads();
    const float scale = sparam[0], zp = sparam[1];

    uint2* dst = reinterpret_cast<uint2*>(g_aq + (size_t)row * K_DIM);
#pragma unroll
    for (int j = 0; j < 8; j++) {
        float q0 = fminf(fmaxf(rintf(__fdiv_rn(v[j].x, scale)) + zp, -128.0f), 127.0f);
        float q1 = fminf(fmaxf(rintf(__fdiv_rn(v[j].y, scale)) + zp, -128.0f), 127.0f);
        float q2 = fminf(fmaxf(rintf(__fdiv_rn(v[j].z, scale)) + zp, -128.0f), 127.0f);
        float q3 = fminf(fmaxf(rintf(__fdiv_rn(v[j].w, scale)) + zp, -128.0f), 127.0f);
        H2U a0, a1;                               // (q - zp): integer in [-255,255], exact in fp16
        a0.h = __floats2half2_rn(q0 - zp, q1 - zp);
        a1.h = __floats2half2_rn(q2 - zp, q3 - zp);
        uint2 u; u.x = a0.u; u.y = a1.u;
        dst[tid + 128 * j] = u;
    }
}

// ---------------------------------------------------------------------------
// Kernel 3: fp16 HMMA GEMM (mma.sync.m16n8k16), CTA tile 128x256, BK=64,
// 4-stage cp.async pipeline (192 KB SMEM, 1 CTA/SM), Swizzle<3,4,3>,
// 8 warps (2M x 4N), warp tile 64x64.  out[m,n] = xscale[m] * acc + bias[n]
// ---------------------------------------------------------------------------
constexpr int BM = 128, BN = 256, STAGES = 4;
constexpr int STAGE_B   = (BM + BN) * 128;        // 48 KB per stage
constexpr int GEMM_SMEM = STAGES * STAGE_B;       // 192 KB
constexpr int NCH       = K_DIM / 64;             // 64 chunks of 64 k

__global__ void __launch_bounds__(256, 1) gemm_kernel(
    const float* __restrict__ bias, float* __restrict__ out)
{
    extern __shared__ char smem[];
    const uint32_t sb = smem_u32(smem);
    const int tid  = threadIdx.x;
    const int lane = tid & 31, wid = tid >> 5;
    const int wm = wid & 1;         // 0..1  -> 64-row slab
    const int wn = wid >> 1;        // 0..3  -> 64-col slab

    const int m0 = blockIdx.y * BM;
    const int n0 = blockIdx.x * BN;
    const char* Ab = reinterpret_cast<const char*>(g_aq)  + (size_t)m0 * (K_DIM * 2);
    const char* Bb = reinterpret_cast<const char*>(g_wdq) + (size_t)n0 * (K_DIM * 2);

    // global->smem mapping: 256 threads x 16B = 4 KB per pass
    const int      lrow = tid >> 3;           // 0..31
    const uint32_t lcol = (uint32_t)(tid & 7) * 16;

    float acc[4][8][4];
#pragma unroll
    for (int a = 0; a < 4; a++)
#pragma unroll
        for (int b = 0; b < 8; b++)
#pragma unroll
            for (int c = 0; c < 4; c++) acc[a][b][c] = 0.0f;

    // ldmatrix per-thread bases
    const int arow = wm * 64 + (lane & 15);            // + mi*16
    const int brow = wn * 64 + (lane & 15);            // + p*16
    const uint32_t fcol = 16u * (uint32_t)(lane >> 4); // + ks*32

#define LOAD_STAGE(stage, chunk)                                               \
    do {                                                                       \
        uint32_t as_ = sb + (stage) * STAGE_B;                                 \
        uint32_t bs_ = as_ + BM * 128;                                         \
        const char* asrc = Ab + (chunk) * 128 + lcol;                          \
        const char* bsrc = Bb + (chunk) * 128 + lcol;                          \
        _Pragma("unroll")                                                      \
        for (int p = 0; p < 4; p++) {                                          \
            int r = lrow + 32 * p;                                             \
            uint32_t sc = lcol ^ (uint32_t)((r & 7) << 4);                     \
            cp16(as_ + (uint32_t)r * 128 + sc, asrc + (size_t)r * 8192);       \
        }                                                                      \
        _Pragma("unroll")                                                      \
        for (int p = 0; p < 8; p++) {                                          \
            int r = lrow + 32 * p;                                             \
            uint32_t sc = lcol ^ (uint32_t)((r & 7) << 4);                     \
            cp16(bs_ + (uint32_t)r * 128 + sc, bsrc + (size_t)r * 8192);       \
        }                                                                      \
    } while (0)

    // prologue: fill STAGES-1 = 3 stages
#pragma unroll
    for (int s = 0; s < STAGES - 1; s++) {
        LOAD_STAGE(s, s);
        asm volatile("cp.async.commit_group;" ::: "memory");
    }

    for (int i = 0; i < NCH; i++) {
        asm volatile("cp.async.wait_group %0;" :: "n"(STAGES - 2) : "memory");
        __syncthreads();

        const int nx = i + STAGES - 1;
        if (nx < NCH) LOAD_STAGE(nx & (STAGES - 1), nx);
        asm volatile("cp.async.commit_group;" ::: "memory");

        const uint32_t as_ = sb + (i & (STAGES - 1)) * STAGE_B;
        const uint32_t bs_ = as_ + BM * 128;
#pragma unroll
        for (int ks = 0; ks < 4; ks++) {
            uint32_t af[4][4], bf[4][4];
            const uint32_t cb = fcol + (uint32_t)(ks * 32);
#pragma unroll
            for (int mi = 0; mi < 4; mi++) {
                int r = arow + mi * 16;
                ldm4(af[mi], as_ + (uint32_t)r * 128 + (cb ^ (uint32_t)((r & 7) << 4)));
            }
#pragma unroll
            for (int p = 0; p < 4; p++) {
                int r = brow + p * 16;
                ldm4(bf[p], bs_ + (uint32_t)r * 128 + (cb ^ (uint32_t)((r & 7) << 4)));
            }
#pragma unroll
            for (int mi = 0; mi < 4; mi++)
#pragma unroll
                for (int nj = 0; nj < 8; nj++)
                    mma16816(acc[mi][nj], af[mi], bf[nj >> 1][nj & 1], bf[nj >> 1][2 + (nj & 1)]);
        }
    }
#undef LOAD_STAGE

    // Epilogue: out = xscale[row] * acc + bias[col]
#pragma unroll
    for (int mi = 0; mi < 4; mi++) {
        const int grow_lo = m0 + wm * 64 + mi * 16 + (lane >> 2);
        const int grow_hi = grow_lo + 8;
        const float sl = g_xscale[grow_lo];
        const float sh = g_xscale[grow_hi];
        float* orow_lo = out + (size_t)grow_lo * N_DIM;
        float* orow_hi = out + (size_t)grow_hi * N_DIM;
#pragma unroll
        for (int nj = 0; nj < 8; nj++) {
            const int gcol = n0 + wn * 64 + nj * 8 + 2 * (lane & 3);
            float2 bv = *reinterpret_cast<const float2*>(bias + gcol);
            float2 o0, o1;
            o0.x = acc[mi][nj][0] * sl + bv.x;
            o0.y = acc[mi][nj][1] * sl + bv.y;
            o1.x = acc[mi][nj][2] * sh + bv.x;
            o1.y = acc[mi][nj][3] * sh + bv.y;
            *reinterpret_cast<float2*>(orow_lo + gcol) = o0;
            *reinterpret_cast<float2*>(orow_hi + gcol) = o1;
        }
    }
}

// ---------------------------------------------------------------------------
// launch
// ---------------------------------------------------------------------------
extern "C" void kernel_launch(void* const* d_in, const int* in_sizes, int n_in,
                              void* d_out, int out_size)
{
    const float* x      = (const float*)d_in[0];
    const void*  w      = d_in[1];                 // dtype detected on device
    const float* scales = (const float*)d_in[2];
    const float* zeros  = (const float*)d_in[3];
    const float* bias   = (const float*)d_in[4];
    float*       out    = (float*)d_out;

    const int rows = in_sizes[0] / K_DIM;   // 8192 tokens

    // 0) detect weight container dtype (int8 vs int32 vs float32)
    detect_wfmt_kernel<<<1, 256>>>((const int*)w);

    // 1) weight dequant -> fp16
    {
        int total = (N_DIM * K_DIM) / 8;
        dequant_w_kernel<<<(total + 255) / 256, 256>>>(w, scales, zeros);
    }
    // 2) activation fake-quant -> exact (q - zp) fp16 + per-row scale
    quant_x_kernel<<<rows, 128>>>(x);

    // 3) GEMM + scale + bias
    cudaFuncSetAttribute(gemm_kernel, cudaFuncAttributeMaxDynamicSharedMemorySize, GEMM_SMEM);
    dim3 grid(N_DIM / BN, rows / BM);
    gemm_kernel<<<grid, 256, GEMM_SMEM>>>(bias, out);
}